// round 1
// baseline (speedup 1.0000x reference)
#include <cuda_runtime.h>

// Problem shape (fixed by the reference)
#define BB 2
#define NN 2048
#define EE 1024
#define HH 16
#define DD 64
#define MM (BB*NN)   // 4096 rows for the projection GEMMs

// Scratch (allocation-free rule: __device__ globals)
__device__ float g_Q[BB*HH*NN*DD];   // [b,h,n,d]  16 MB
__device__ float g_K[BB*HH*NN*DD];   // 16 MB
__device__ float g_V[BB*HH*NN*DD];   // 16 MB
__device__ float g_AO[BB*NN*EE];     // [b,n,e]    16 MB

// ---------------------------------------------------------------------------
// GEMM: C[M=4096][1024] = X[4096][1024] @ W[1024][1024]^T + bias
// target 0/1/2 -> split-head write into g_Q/g_K/g_V ([b,h,n,d])
// target 3     -> row-major write to outp, X taken from g_AO
// Tile: BM=BN=64, BK=16, 256 threads, 4x4 microtile.
// ---------------------------------------------------------------------------
__global__ __launch_bounds__(256)
void gemm_kernel(const float* __restrict__ Xin, const float* __restrict__ W,
                 const float* __restrict__ bias, float* __restrict__ outp,
                 int target)
{
    const float* __restrict__ X = (target == 3) ? (const float*)g_AO : Xin;

    __shared__ float As[16][64];
    __shared__ float Bs[16][64];

    const int tid = threadIdx.x;
    const int m0  = blockIdx.y * 64;
    const int n0  = blockIdx.x * 64;
    const int tm  = tid >> 4;       // 0..15
    const int tn  = tid & 15;       // 0..15

    // load mapping: each thread brings one float4 per operand per k-tile
    const int lr = tid >> 2;        // 0..63 (tile row)
    const int lk = (tid & 3) * 4;   // 0,4,8,12 (k offset)

    float acc[4][4];
    #pragma unroll
    for (int i = 0; i < 4; i++)
        #pragma unroll
        for (int j = 0; j < 4; j++) acc[i][j] = 0.f;

    for (int k0 = 0; k0 < 1024; k0 += 16) {
        float4 a = *(const float4*)&X[(m0 + lr) * 1024 + k0 + lk];
        float4 b = *(const float4*)&W[(n0 + lr) * 1024 + k0 + lk];
        As[lk + 0][lr] = a.x; As[lk + 1][lr] = a.y;
        As[lk + 2][lr] = a.z; As[lk + 3][lr] = a.w;
        Bs[lk + 0][lr] = b.x; Bs[lk + 1][lr] = b.y;
        Bs[lk + 2][lr] = b.z; Bs[lk + 3][lr] = b.w;
        __syncthreads();

        #pragma unroll
        for (int kk = 0; kk < 16; kk++) {
            float4 av = *(const float4*)&As[kk][tm * 4];
            float4 bv = *(const float4*)&Bs[kk][tn * 4];
            float aa[4] = {av.x, av.y, av.z, av.w};
            float bb[4] = {bv.x, bv.y, bv.z, bv.w};
            #pragma unroll
            for (int i = 0; i < 4; i++)
                #pragma unroll
                for (int j = 0; j < 4; j++)
                    acc[i][j] = fmaf(aa[i], bb[j], acc[i][j]);
        }
        __syncthreads();
    }

    #pragma unroll
    for (int i = 0; i < 4; i++) {
        const int m = m0 + tm * 4 + i;
        #pragma unroll
        for (int j = 0; j < 4; j++) {
            const int c = n0 + tn * 4 + j;
            float v = acc[i][j] + bias[c];
            if (target == 3) {
                outp[m * 1024 + c] = v;
            } else {
                const int b = m >> 11;       // m / NN
                const int n = m & (NN - 1);
                const int h = c >> 6;        // c / DD
                const int d = c & (DD - 1);
                float* dst = (target == 0) ? g_Q : (target == 1) ? g_K : g_V;
                dst[((b * HH + h) * NN + n) * DD + d] = v;
            }
        }
    }
}

// ---------------------------------------------------------------------------
// Flash-style attention, one thread per query row.
// grid = (B*H, N/128), block = 128 threads.
// out = (softmax(QK^T) / sqrt(E)) @ V  ->  g_AO in [b,n,e]
// ---------------------------------------------------------------------------
__global__ __launch_bounds__(128)
void attn_kernel()
{
    const int bh = blockIdx.x;                       // 0..31
    const int q  = blockIdx.y * 128 + threadIdx.x;   // query index in-head

    const float* __restrict__ Qp = g_Q + (size_t)bh * NN * DD;
    const float* __restrict__ Kp = g_K + (size_t)bh * NN * DD;
    const float* __restrict__ Vp = g_V + (size_t)bh * NN * DD;

    __shared__ float Ks[64 * 64];
    __shared__ float Vs[64 * 64];

    float qr[64];
    {
        const float4* qsrc = (const float4*)(Qp + (size_t)q * DD);
        #pragma unroll
        for (int d4 = 0; d4 < 16; d4++) {
            float4 v = qsrc[d4];
            qr[4 * d4 + 0] = v.x; qr[4 * d4 + 1] = v.y;
            qr[4 * d4 + 2] = v.z; qr[4 * d4 + 3] = v.w;
        }
    }

    float o[64];
    #pragma unroll
    for (int d = 0; d < 64; d++) o[d] = 0.f;
    float m = -1e30f, l = 0.f;

    for (int k0 = 0; k0 < NN; k0 += 64) {
        // cooperative tile load: 64 keys x 64 dims each for K and V (16 KB each)
        const float4* ksrc = (const float4*)(Kp + (size_t)k0 * DD);
        const float4* vsrc = (const float4*)(Vp + (size_t)k0 * DD);
        float4* kd = (float4*)Ks;
        float4* vd = (float4*)Vs;
        #pragma unroll
        for (int i = 0; i < 8; i++) {
            kd[threadIdx.x + i * 128] = ksrc[threadIdx.x + i * 128];
            vd[threadIdx.x + i * 128] = vsrc[threadIdx.x + i * 128];
        }
        __syncthreads();

        for (int j = 0; j < 64; j++) {
            // s = q . K[j]  (smem broadcast across all threads)
            const float4* kr4 = (const float4*)(Ks + j * 64);
            float s = 0.f;
            #pragma unroll
            for (int d4 = 0; d4 < 16; d4++) {
                float4 kv = kr4[d4];
                s = fmaf(qr[4 * d4 + 0], kv.x, s);
                s = fmaf(qr[4 * d4 + 1], kv.y, s);
                s = fmaf(qr[4 * d4 + 2], kv.z, s);
                s = fmaf(qr[4 * d4 + 3], kv.w, s);
            }
            const float mnew = fmaxf(m, s);
            const float corr = __expf(m - mnew);   // 1.0f when max unchanged
            const float p    = __expf(s - mnew);
            l = l * corr + p;

            const float4* vr4 = (const float4*)(Vs + j * 64);
            #pragma unroll
            for (int d4 = 0; d4 < 16; d4++) {
                float4 vv = vr4[d4];
                o[4 * d4 + 0] = fmaf(p, vv.x, o[4 * d4 + 0] * corr);
                o[4 * d4 + 1] = fmaf(p, vv.y, o[4 * d4 + 1] * corr);
                o[4 * d4 + 2] = fmaf(p, vv.z, o[4 * d4 + 2] * corr);
                o[4 * d4 + 3] = fmaf(p, vv.w, o[4 * d4 + 3] * corr);
            }
            m = mnew;
        }
        __syncthreads();
    }

    // epilogue: softmax normalization AND the reference's /sqrt(E) (=32)
    const int b = bh / HH;
    const int h = bh % HH;
    const float inv = 1.0f / (l * 32.0f);
    float* dst = g_AO + ((size_t)(b * NN + q)) * EE + h * DD;
    #pragma unroll
    for (int d = 0; d < 64; d++) dst[d] = o[d] * inv;
}

// ---------------------------------------------------------------------------
extern "C" void kernel_launch(void* const* d_in, const int* in_sizes, int n_in,
                              void* d_out, int out_size)
{
    const float* x  = (const float*)d_in[0];
    const float* Wq = (const float*)d_in[1];
    const float* bq = (const float*)d_in[2];
    const float* Wk = (const float*)d_in[3];
    const float* bk = (const float*)d_in[4];
    const float* Wv = (const float*)d_in[5];
    const float* bv = (const float*)d_in[6];
    const float* Wo = (const float*)d_in[7];
    const float* bo = (const float*)d_in[8];
    float* out = (float*)d_out;

    dim3 ggrid(EE / 64, MM / 64);   // (16, 64)
    gemm_kernel<<<ggrid, 256>>>(x, Wq, bq, nullptr, 0);
    gemm_kernel<<<ggrid, 256>>>(x, Wk, bk, nullptr, 1);
    gemm_kernel<<<ggrid, 256>>>(x, Wv, bv, nullptr, 2);

    dim3 agrid(BB * HH, NN / 128);  // (32, 16)
    attn_kernel<<<agrid, 128>>>();

    gemm_kernel<<<ggrid, 256>>>(nullptr, Wo, bo, out, 3);
}

// round 3
// speedup vs baseline: 3.1848x; 3.1848x over previous
#include <cuda_runtime.h>
#include <cstdint>

#define BB 2
#define NN 2048
#define EE 1024
#define HH 16
#define DD 64
#define MM (BB*NN)

// Scratch (allocation-free rule: __device__ globals)
__device__ float g_Q[BB*HH*NN*DD];   // [b,h,n,d]
__device__ float g_K[BB*HH*NN*DD];
__device__ float g_V[BB*HH*NN*DD];
__device__ float g_AO[BB*NN*EE];     // [b,n,e]

__device__ __forceinline__ uint32_t f2tf(float f) {
    uint32_t u;
    asm("cvt.rna.tf32.f32 %0, %1;" : "=r"(u) : "f"(f));
    return u;
}

__device__ __forceinline__ void mma_tf32(float* d, const uint32_t* a, const uint32_t* b) {
    asm volatile(
        "mma.sync.aligned.m16n8k8.row.col.f32.tf32.tf32.f32 "
        "{%0,%1,%2,%3}, {%4,%5,%6,%7}, {%8,%9}, {%0,%1,%2,%3};"
        : "+f"(d[0]), "+f"(d[1]), "+f"(d[2]), "+f"(d[3])
        : "r"(a[0]), "r"(a[1]), "r"(a[2]), "r"(a[3]), "r"(b[0]), "r"(b[1]));
}

// ---------------------------------------------------------------------------
// tf32 tensor-core GEMM: C[4096][1024] = X @ W^T + bias
// Block tile 64x64, BK=16, 4 warps (2x2), warp tile 32x32, double-buffered.
// target 0/1/2 -> split-head write to g_Q/g_K/g_V; target 3 -> outp (X=g_AO)
// ---------------------------------------------------------------------------
#define GS 20   // smem row stride (floats): conflict-free for frag loads, 16B-aligned rows

__global__ __launch_bounds__(128)
void gemm_tc(const float* __restrict__ Xin, const float* __restrict__ W,
             const float* __restrict__ bias, float* __restrict__ outp, int target)
{
    const float* __restrict__ X = (target == 3) ? (const float*)g_AO : Xin;

    __shared__ uint32_t As[2][64 * GS];
    __shared__ uint32_t Ws[2][64 * GS];

    const int tid  = threadIdx.x;
    const int warp = tid >> 5, lane = tid & 31;
    const int g = lane >> 2, t = lane & 3;
    const int m0 = blockIdx.y * 64, n0 = blockIdx.x * 64;
    const int wm = (warp >> 1) * 32, wn = (warp & 1) * 32;

    float acc[2][4][4];
    #pragma unroll
    for (int i = 0; i < 2; i++)
        #pragma unroll
        for (int j = 0; j < 4; j++)
            #pragma unroll
            for (int k = 0; k < 4; k++) acc[i][j][k] = 0.f;

    // each thread loads 2 float4 per matrix per k-tile
    const int r0 = tid >> 2;                 // rows for idx=tid
    const int c0 = (tid & 3) * 4;
    const int r1 = (tid + 128) >> 2;
    const int c1 = ((tid + 128) & 3) * 4;

    float4 ra0, ra1, rw0, rw1;

    // prologue: tile 0
    ra0 = *(const float4*)&X[(m0 + r0) * 1024 + 0 + c0];
    ra1 = *(const float4*)&X[(m0 + r1) * 1024 + 0 + c1];
    rw0 = *(const float4*)&W[(n0 + r0) * 1024 + 0 + c0];
    rw1 = *(const float4*)&W[(n0 + r1) * 1024 + 0 + c1];
    {
        uint32_t* p;
        p = &As[0][r0 * GS + c0]; p[0]=f2tf(ra0.x); p[1]=f2tf(ra0.y); p[2]=f2tf(ra0.z); p[3]=f2tf(ra0.w);
        p = &As[0][r1 * GS + c1]; p[0]=f2tf(ra1.x); p[1]=f2tf(ra1.y); p[2]=f2tf(ra1.z); p[3]=f2tf(ra1.w);
        p = &Ws[0][r0 * GS + c0]; p[0]=f2tf(rw0.x); p[1]=f2tf(rw0.y); p[2]=f2tf(rw0.z); p[3]=f2tf(rw0.w);
        p = &Ws[0][r1 * GS + c1]; p[0]=f2tf(rw1.x); p[1]=f2tf(rw1.y); p[2]=f2tf(rw1.z); p[3]=f2tf(rw1.w);
    }
    __syncthreads();

    for (int kt = 0; kt < 64; kt++) {
        const int buf = kt & 1;
        if (kt < 63) {
            const int k0 = (kt + 1) * 16;
            ra0 = *(const float4*)&X[(m0 + r0) * 1024 + k0 + c0];
            ra1 = *(const float4*)&X[(m0 + r1) * 1024 + k0 + c1];
            rw0 = *(const float4*)&W[(n0 + r0) * 1024 + k0 + c0];
            rw1 = *(const float4*)&W[(n0 + r1) * 1024 + k0 + c1];
        }

        #pragma unroll
        for (int ks = 0; ks < 16; ks += 8) {
            uint32_t af[2][4], bf[4][2];
            #pragma unroll
            for (int mi = 0; mi < 2; mi++) {
                const int row = wm + mi * 16 + g;
                af[mi][0] = As[buf][row * GS + ks + t];
                af[mi][1] = As[buf][(row + 8) * GS + ks + t];
                af[mi][2] = As[buf][row * GS + ks + t + 4];
                af[mi][3] = As[buf][(row + 8) * GS + ks + t + 4];
            }
            #pragma unroll
            for (int nt = 0; nt < 4; nt++) {
                const int nr = wn + nt * 8 + g;
                bf[nt][0] = Ws[buf][nr * GS + ks + t];
                bf[nt][1] = Ws[buf][nr * GS + ks + t + 4];
            }
            #pragma unroll
            for (int mi = 0; mi < 2; mi++)
                #pragma unroll
                for (int nt = 0; nt < 4; nt++)
                    mma_tf32(acc[mi][nt], af[mi], bf[nt]);
        }

        if (kt < 63) {
            const int nb = buf ^ 1;
            uint32_t* p;
            p = &As[nb][r0 * GS + c0]; p[0]=f2tf(ra0.x); p[1]=f2tf(ra0.y); p[2]=f2tf(ra0.z); p[3]=f2tf(ra0.w);
            p = &As[nb][r1 * GS + c1]; p[0]=f2tf(ra1.x); p[1]=f2tf(ra1.y); p[2]=f2tf(ra1.z); p[3]=f2tf(ra1.w);
            p = &Ws[nb][r0 * GS + c0]; p[0]=f2tf(rw0.x); p[1]=f2tf(rw0.y); p[2]=f2tf(rw0.z); p[3]=f2tf(rw0.w);
            p = &Ws[nb][r1 * GS + c1]; p[0]=f2tf(rw1.x); p[1]=f2tf(rw1.y); p[2]=f2tf(rw1.z); p[3]=f2tf(rw1.w);
            __syncthreads();
        }
    }

    // epilogue
    float* dstQKV = (target == 0) ? g_Q : (target == 1) ? g_K : g_V;
    #pragma unroll
    for (int mi = 0; mi < 2; mi++) {
        #pragma unroll
        for (int nt = 0; nt < 4; nt++) {
            const int rbase = m0 + wm + mi * 16 + g;
            const int cbase = n0 + wn + nt * 8 + 2 * t;
            #pragma unroll
            for (int hh = 0; hh < 2; hh++) {          // hh: +0 / +8 row
                const int m = rbase + hh * 8;
                const float v0 = acc[mi][nt][2 * hh + 0] + bias[cbase + 0];
                const float v1 = acc[mi][nt][2 * hh + 1] + bias[cbase + 1];
                if (target == 3) {
                    outp[m * 1024 + cbase + 0] = v0;
                    outp[m * 1024 + cbase + 1] = v1;
                } else {
                    const int b = m >> 11;
                    const int n = m & (NN - 1);
                    const int h = cbase >> 6;
                    const int d = cbase & (DD - 1);
                    float* p = &dstQKV[((b * HH + h) * NN + n) * DD + d];
                    p[0] = v0; p[1] = v1;
                }
            }
        }
    }
}

// ---------------------------------------------------------------------------
// Flash attention with tf32 MMA.
// grid = (B*H, N/64), block = 128 (4 warps x 16 query rows).
// Key tiles of 32. out = (softmax(QK^T)/32) @ V -> g_AO [b,n,e]
// ---------------------------------------------------------------------------
#define KST 68   // Ks/Qs row stride
#define VST 72   // Vs row stride
#define PST 36   // Ps row stride
// smem layout (uint32 words): Ks @0 (32*68=2176), Vs @2176 (32*72=2304),
// Ps @4480 (4 warps * 16*36=576). Qs (64*68=4352) aliases Ks+Vs during staging.
#define SM_WORDS (4480 + 4*576)

__global__ __launch_bounds__(128)
void attn_tc()
{
    __shared__ uint32_t sm[SM_WORDS];

    const int bh = blockIdx.x;
    const int q0 = blockIdx.y * 64;
    const int tid = threadIdx.x, warp = tid >> 5, lane = tid & 31;
    const int g = lane >> 2, t = lane & 3;

    const float* __restrict__ Qp = g_Q + (size_t)bh * NN * DD;
    const float* __restrict__ Kp = g_K + (size_t)bh * NN * DD;
    const float* __restrict__ Vp = g_V + (size_t)bh * NN * DD;

    uint32_t* const Qs = sm;
    uint32_t* const Ks = sm;
    uint32_t* const Vs = sm + 2176;
    uint32_t* const Ps = sm + 4480 + warp * (16 * PST);

    // stage Q tile (64x64) and hoist fragments to registers
    for (int i = tid; i < 64 * 16; i += 128) {
        const int r = i >> 4, c4 = (i & 15) * 4;
        float4 v = *(const float4*)&Qp[(size_t)(q0 + r) * DD + c4];
        uint32_t* p = &Qs[r * KST + c4];
        p[0]=f2tf(v.x); p[1]=f2tf(v.y); p[2]=f2tf(v.z); p[3]=f2tf(v.w);
    }
    __syncthreads();

    uint32_t qa[8][4];
    const int qrow = warp * 16 + g;
    #pragma unroll
    for (int ks = 0; ks < 8; ks++) {
        qa[ks][0] = Qs[qrow * KST + ks * 8 + t];
        qa[ks][1] = Qs[(qrow + 8) * KST + ks * 8 + t];
        qa[ks][2] = Qs[qrow * KST + ks * 8 + t + 4];
        qa[ks][3] = Qs[(qrow + 8) * KST + ks * 8 + t + 4];
    }
    __syncthreads();   // done reading Qs before K/V overwrite

    float O[8][4];
    #pragma unroll
    for (int i = 0; i < 8; i++)
        #pragma unroll
        for (int j = 0; j < 4; j++) O[i][j] = 0.f;
    float m1 = -1e30f, m2 = -1e30f, l1 = 0.f, l2 = 0.f;

    for (int kt = 0; kt < NN; kt += 32) {
        // load K,V tile (32x64 each)
        #pragma unroll
        for (int i = 0; i < 4; i++) {
            const int idx = tid + i * 128;          // 0..511 float4s
            const int r = idx >> 4, c4 = (idx & 15) * 4;
            float4 kv = *(const float4*)&Kp[(size_t)(kt + r) * DD + c4];
            uint32_t* pk = &Ks[r * KST + c4];
            pk[0]=f2tf(kv.x); pk[1]=f2tf(kv.y); pk[2]=f2tf(kv.z); pk[3]=f2tf(kv.w);
            float4 vv = *(const float4*)&Vp[(size_t)(kt + r) * DD + c4];
            uint32_t* pv = &Vs[r * VST + c4];
            pv[0]=f2tf(vv.x); pv[1]=f2tf(vv.y); pv[2]=f2tf(vv.z); pv[3]=f2tf(vv.w);
        }
        __syncthreads();

        // S = Q K^T   (16 x 32 per warp)
        float S[4][4];
        #pragma unroll
        for (int i = 0; i < 4; i++)
            #pragma unroll
            for (int j = 0; j < 4; j++) S[i][j] = 0.f;

        #pragma unroll
        for (int ks = 0; ks < 8; ks++) {
            #pragma unroll
            for (int nt = 0; nt < 4; nt++) {
                uint32_t bf[2];
                const int key = nt * 8 + g;
                bf[0] = Ks[key * KST + ks * 8 + t];
                bf[1] = Ks[key * KST + ks * 8 + t + 4];
                mma_tf32(S[nt], qa[ks], bf);
            }
        }

        // online softmax on the C-fragment layout
        float rmax1 = -1e30f, rmax2 = -1e30f;
        #pragma unroll
        for (int nt = 0; nt < 4; nt++) {
            rmax1 = fmaxf(rmax1, fmaxf(S[nt][0], S[nt][1]));
            rmax2 = fmaxf(rmax2, fmaxf(S[nt][2], S[nt][3]));
        }
        rmax1 = fmaxf(rmax1, __shfl_xor_sync(0xffffffff, rmax1, 1));
        rmax1 = fmaxf(rmax1, __shfl_xor_sync(0xffffffff, rmax1, 2));
        rmax2 = fmaxf(rmax2, __shfl_xor_sync(0xffffffff, rmax2, 1));
        rmax2 = fmaxf(rmax2, __shfl_xor_sync(0xffffffff, rmax2, 2));

        const float mn1 = fmaxf(m1, rmax1);
        const float mn2 = fmaxf(m2, rmax2);
        const float cr1 = __expf(m1 - mn1);
        const float cr2 = __expf(m2 - mn2);

        float P[4][4];
        float rs1 = 0.f, rs2 = 0.f;
        #pragma unroll
        for (int nt = 0; nt < 4; nt++) {
            P[nt][0] = __expf(S[nt][0] - mn1);
            P[nt][1] = __expf(S[nt][1] - mn1);
            P[nt][2] = __expf(S[nt][2] - mn2);
            P[nt][3] = __expf(S[nt][3] - mn2);
            rs1 += P[nt][0] + P[nt][1];
            rs2 += P[nt][2] + P[nt][3];
        }
        rs1 += __shfl_xor_sync(0xffffffff, rs1, 1);
        rs1 += __shfl_xor_sync(0xffffffff, rs1, 2);
        rs2 += __shfl_xor_sync(0xffffffff, rs2, 1);
        rs2 += __shfl_xor_sync(0xffffffff, rs2, 2);

        l1 = l1 * cr1 + rs1;
        l2 = l2 * cr2 + rs2;
        m1 = mn1; m2 = mn2;

        #pragma unroll
        for (int nt = 0; nt < 8; nt++) {
            O[nt][0] *= cr1; O[nt][1] *= cr1;
            O[nt][2] *= cr2; O[nt][3] *= cr2;
        }

        // re-fragment P through per-warp smem tile
        __syncwarp();
        #pragma unroll
        for (int nt = 0; nt < 4; nt++) {
            Ps[g * PST + nt * 8 + 2 * t]           = f2tf(P[nt][0]);
            Ps[g * PST + nt * 8 + 2 * t + 1]       = f2tf(P[nt][1]);
            Ps[(g + 8) * PST + nt * 8 + 2 * t]     = f2tf(P[nt][2]);
            Ps[(g + 8) * PST + nt * 8 + 2 * t + 1] = f2tf(P[nt][3]);
        }
        __syncwarp();

        // O += P V
        #pragma unroll
        for (int ks = 0; ks < 4; ks++) {
            uint32_t pa[4];
            pa[0] = Ps[g * PST + ks * 8 + t];
            pa[1] = Ps[(g + 8) * PST + ks * 8 + t];
            pa[2] = Ps[g * PST + ks * 8 + t + 4];
            pa[3] = Ps[(g + 8) * PST + ks * 8 + t + 4];
            #pragma unroll
            for (int nt = 0; nt < 8; nt++) {
                uint32_t bf[2];
                bf[0] = Vs[(ks * 8 + t) * VST + nt * 8 + g];
                bf[1] = Vs[(ks * 8 + t + 4) * VST + nt * 8 + g];
                mma_tf32(O[nt], pa, bf);
            }
        }
        __syncthreads();   // before next tile overwrites Ks/Vs
    }

    // epilogue: softmax norm AND the reference's /sqrt(E)=32
    const int b = bh / HH, h = bh % HH;
    const int q1 = q0 + warp * 16 + g;
    const int q2 = q1 + 8;
    const float i1 = 1.0f / (l1 * 32.0f);
    const float i2 = 1.0f / (l2 * 32.0f);
    float* d1 = g_AO + ((size_t)(b * NN + q1)) * EE + h * DD;
    float* d2 = g_AO + ((size_t)(b * NN + q2)) * EE + h * DD;
    #pragma unroll
    for (int nt = 0; nt < 8; nt++) {
        d1[nt * 8 + 2 * t]     = O[nt][0] * i1;
        d1[nt * 8 + 2 * t + 1] = O[nt][1] * i1;
        d2[nt * 8 + 2 * t]     = O[nt][2] * i2;
        d2[nt * 8 + 2 * t + 1] = O[nt][3] * i2;
    }
}

// ---------------------------------------------------------------------------
extern "C" void kernel_launch(void* const* d_in, const int* in_sizes, int n_in,
                              void* d_out, int out_size)
{
    const float* x  = (const float*)d_in[0];
    const float* Wq = (const float*)d_in[1];
    const float* bq = (const float*)d_in[2];
    const float* Wk = (const float*)d_in[3];
    const float* bk = (const float*)d_in[4];
    const float* Wv = (const float*)d_in[5];
    const float* bv = (const float*)d_in[6];
    const float* Wo = (const float*)d_in[7];
    const float* bo = (const float*)d_in[8];
    float* out = (float*)d_out;

    dim3 ggrid(EE / 64, MM / 64);   // (16, 64)
    gemm_tc<<<ggrid, 128>>>(x, Wq, bq, nullptr, 0);
    gemm_tc<<<ggrid, 128>>>(x, Wk, bk, nullptr, 1);
    gemm_tc<<<ggrid, 128>>>(x, Wv, bv, nullptr, 2);

    dim3 agrid(BB * HH, NN / 64);   // (32, 32)
    attn_tc<<<agrid, 128>>>();

    gemm_tc<<<ggrid, 128>>>(nullptr, Wo, bo, out, 3);
}

// round 6
// speedup vs baseline: 4.2671x; 1.3398x over previous
#include <cuda_runtime.h>
#include <cstdint>

#define BB 2
#define NN 2048
#define EE 1024
#define HH 16
#define DD 64
#define MM (BB*NN)

// All scratch pre-converted to tf32 (stored as uint32 payloads).
__device__ uint32_t g_Xt[MM*EE];          // x in tf32
__device__ uint32_t g_Wt[4][EE*EE];       // Wq,Wk,Wv,Wo in tf32
__device__ uint32_t g_Q[BB*HH*NN*DD];     // [b,h,n,d] tf32
__device__ uint32_t g_K[BB*HH*NN*DD];
__device__ uint32_t g_V[BB*HH*NN*DD];
__device__ uint32_t g_AOt[BB*NN*EE];      // attn out, [b,n,e] tf32

__device__ __forceinline__ uint32_t f2tf(float f) {
    uint32_t u;
    asm("cvt.rna.tf32.f32 %0, %1;" : "=r"(u) : "f"(f));
    return u;
}
__device__ __forceinline__ void mma_tf32(float* d, const uint32_t* a, const uint32_t* b) {
    asm volatile(
        "mma.sync.aligned.m16n8k8.row.col.f32.tf32.tf32.f32 "
        "{%0,%1,%2,%3}, {%4,%5,%6,%7}, {%8,%9}, {%0,%1,%2,%3};"
        : "+f"(d[0]), "+f"(d[1]), "+f"(d[2]), "+f"(d[3])
        : "r"(a[0]), "r"(a[1]), "r"(a[2]), "r"(a[3]), "r"(b[0]), "r"(b[1]));
}
__device__ __forceinline__ void cpa16(uint32_t s, const void* g) {
    asm volatile("cp.async.cg.shared.global [%0], [%1], 16;" :: "r"(s), "l"(g));
}
__device__ __forceinline__ void cp_commit() { asm volatile("cp.async.commit_group;"); }
template<int N> __device__ __forceinline__ void cp_wait() {
    asm volatile("cp.async.wait_group %0;" :: "n"(N));
}

// ---------------------------------------------------------------------------
// Pre-pass: fp32 -> tf32 (RNA) bulk convert. which: 0=x, 1..4=Wq..Wo
// ---------------------------------------------------------------------------
__global__ __launch_bounds__(256)
void conv_tf32(const float4* __restrict__ src, int which, int n4)
{
    uint4* dst = (which == 0) ? (uint4*)g_Xt : (uint4*)g_Wt[which - 1];
    int i = blockIdx.x * 256 + threadIdx.x;
    if (i < n4) {
        float4 v = src[i];
        uint4 u;
        u.x = f2tf(v.x); u.y = f2tf(v.y); u.z = f2tf(v.z); u.w = f2tf(v.w);
        dst[i] = u;
    }
}

// ---------------------------------------------------------------------------
// tf32 GEMM: C[4096][1024] = X @ W^T + bias.  128x128x16 tiles, 256 thr,
// 3-stage cp.async.  target=-1: QKV (tgt=blockIdx.z, write g_Q/K/V tf32
// split-head); target=3: O-proj (X=g_AOt, write fp32 to outp).
// ---------------------------------------------------------------------------
#define GS 20
#define GST (128*GS)            // 2560 words per stage per matrix
#define GEMM_SMEM (6*GST*4)     // 61440 B

__global__ __launch_bounds__(256)
void gemm_tc(const float* __restrict__ b0, const float* __restrict__ b1,
             const float* __restrict__ b2, const float* __restrict__ b3,
             float* __restrict__ outp, int target)
{
    const int tgt = (target < 0) ? (int)blockIdx.z : target;
    const uint32_t* __restrict__ X = (tgt == 3) ? g_AOt : g_Xt;
    const uint32_t* __restrict__ W = g_Wt[tgt];
    const float* __restrict__ bias = (tgt == 0) ? b0 : (tgt == 1) ? b1 : (tgt == 2) ? b2 : b3;

    extern __shared__ uint32_t sm[];
    uint32_t* As = sm;
    uint32_t* Ws = sm + 3 * GST;
    const uint32_t sbA = (uint32_t)__cvta_generic_to_shared(sm);
    const uint32_t sbW = sbA + 3 * GST * 4;

    const int tid = threadIdx.x;
    const int warp = tid >> 5, lane = tid & 31;
    const int g = lane >> 2, t = lane & 3;
    const int m0 = blockIdx.y * 128, n0 = blockIdx.x * 128;
    const int wm = (warp >> 1) * 32, wn = (warp & 1) * 64;

    const int r0 = tid >> 2,         c0 = (tid & 3) * 4;
    const int r1 = (tid + 256) >> 2, c1 = ((tid + 256) & 3) * 4;

    float acc[2][8][4];
    #pragma unroll
    for (int i = 0; i < 2; i++)
        #pragma unroll
        for (int j = 0; j < 8; j++)
            #pragma unroll
            for (int k = 0; k < 4; k++) acc[i][j][k] = 0.f;

    auto issue = [&](int s, int kk) {
        const uint32_t ao = sbA + (uint32_t)(s * GST) * 4;
        const uint32_t wo = sbW + (uint32_t)(s * GST) * 4;
        cpa16(ao + (r0 * GS + c0) * 4, X + (size_t)(m0 + r0) * EE + kk * 16 + c0);
        cpa16(ao + (r1 * GS + c1) * 4, X + (size_t)(m0 + r1) * EE + kk * 16 + c1);
        cpa16(wo + (r0 * GS + c0) * 4, W + (size_t)(n0 + r0) * EE + kk * 16 + c0);
        cpa16(wo + (r1 * GS + c1) * 4, W + (size_t)(n0 + r1) * EE + kk * 16 + c1);
        cp_commit();
    };

    issue(0, 0);
    issue(1, 1);

    for (int kt = 0; kt < 64; kt++) {
        const int buf = kt % 3;
        if (kt < 63) cp_wait<1>(); else cp_wait<0>();
        __syncthreads();
        if (kt + 2 < 64) issue((kt + 2) % 3, kt + 2);

        const uint32_t* Ab = As + buf * GST;
        const uint32_t* Wb = Ws + buf * GST;
        #pragma unroll
        for (int ks = 0; ks < 16; ks += 8) {
            uint32_t af[2][4];
            #pragma unroll
            for (int mi = 0; mi < 2; mi++) {
                const int row = wm + mi * 16 + g;
                af[mi][0] = Ab[row * GS + ks + t];
                af[mi][1] = Ab[(row + 8) * GS + ks + t];
                af[mi][2] = Ab[row * GS + ks + t + 4];
                af[mi][3] = Ab[(row + 8) * GS + ks + t + 4];
            }
            #pragma unroll
            for (int nt = 0; nt < 8; nt++) {
                uint32_t bf[2];
                const int nr = wn + nt * 8 + g;
                bf[0] = Wb[nr * GS + ks + t];
                bf[1] = Wb[nr * GS + ks + t + 4];
                mma_tf32(acc[0][nt], af[0], bf);
                mma_tf32(acc[1][nt], af[1], bf);
            }
        }
        __syncthreads();
    }

    // epilogue
    uint32_t* dstQKV = (tgt == 0) ? g_Q : (tgt == 1) ? g_K : g_V;
    #pragma unroll
    for (int mi = 0; mi < 2; mi++) {
        #pragma unroll
        for (int nt = 0; nt < 8; nt++) {
            const int rbase = m0 + wm + mi * 16 + g;
            const int cbase = n0 + wn + nt * 8 + 2 * t;
            #pragma unroll
            for (int hh = 0; hh < 2; hh++) {
                const int m = rbase + hh * 8;
                const float v0 = acc[mi][nt][2 * hh + 0] + bias[cbase + 0];
                const float v1 = acc[mi][nt][2 * hh + 1] + bias[cbase + 1];
                if (tgt == 3) {
                    outp[m * EE + cbase + 0] = v0;
                    outp[m * EE + cbase + 1] = v1;
                } else {
                    const int b = m >> 11;
                    const int n = m & (NN - 1);
                    const int h = cbase >> 6;
                    const int d = cbase & (DD - 1);
                    uint32_t* p = &dstQKV[((b * HH + h) * NN + n) * DD + d];
                    p[0] = f2tf(v0); p[1] = f2tf(v1);
                }
            }
        }
    }
}

// ---------------------------------------------------------------------------
// Flash attention, tf32 MMA, 64-key tiles, 2-stage cp.async.
// grid (B*H, N/64), block 128 (4 warps x 16 q-rows).
// ---------------------------------------------------------------------------
#define KST 68
#define VST 72
#define PST 68
#define VS_OFF  8704                 // 2 stages * 64*KST = 8704 words for K
#define PS_OFF  17920                // VS_OFF + 2 * 64*VST
#define ATTN_SMEM ((PS_OFF + 4*16*PST) * 4)   // 89088 B

__global__ __launch_bounds__(128)
void attn_tc()
{
    extern __shared__ uint32_t sm[];
    const uint32_t sb = (uint32_t)__cvta_generic_to_shared(sm);

    const int bh = blockIdx.x;
    const int q0 = blockIdx.y * 64;
    const int tid = threadIdx.x, warp = tid >> 5, lane = tid & 31;
    const int g = lane >> 2, t = lane & 3;

    const uint32_t* __restrict__ Qp = g_Q + (size_t)bh * NN * DD;
    const uint32_t* __restrict__ Kp = g_K + (size_t)bh * NN * DD;
    const uint32_t* __restrict__ Vp = g_V + (size_t)bh * NN * DD;

    // Full 64x64-word tile copy: 1024 float4s over 128 threads = 8 per thread.
    auto issueK = [&](int s, int kk) {
        const uint32_t off = sb + (uint32_t)(s * 64 * KST) * 4;
        #pragma unroll
        for (int i = 0; i < 8; i++) {
            const int idx = tid + i * 128;          // 0..1023
            const int r = idx >> 4, c4 = (idx & 15) * 4;
            cpa16(off + (r * KST + c4) * 4, Kp + (size_t)(kk * 64 + r) * DD + c4);
        }
    };
    auto issueV = [&](int s, int kk) {
        const uint32_t off = sb + (uint32_t)(VS_OFF + s * 64 * VST) * 4;
        #pragma unroll
        for (int i = 0; i < 8; i++) {
            const int idx = tid + i * 128;
            const int r = idx >> 4, c4 = (idx & 15) * 4;
            cpa16(off + (r * VST + c4) * 4, Vp + (size_t)(kk * 64 + r) * DD + c4);
        }
    };

    // Q -> V stage-0 region (free until V tile0 lands), K tile0 -> K stage 0
    {
        const uint32_t qoff = sb + (uint32_t)VS_OFF * 4;
        #pragma unroll
        for (int i = 0; i < 8; i++) {
            const int idx = tid + i * 128;
            const int r = idx >> 4, c4 = (idx & 15) * 4;
            cpa16(qoff + (r * KST + c4) * 4, Qp + (size_t)(q0 + r) * DD + c4);
        }
        cp_commit();
        issueK(0, 0);
        cp_commit();
    }
    cp_wait<1>();            // Q group done (K0 may still be in flight)
    __syncthreads();

    uint32_t qa[8][4];
    {
        const uint32_t* Qs = sm + VS_OFF;
        const int qrow = warp * 16 + g;
        #pragma unroll
        for (int ks = 0; ks < 8; ks++) {
            qa[ks][0] = Qs[qrow * KST + ks * 8 + t];
            qa[ks][1] = Qs[(qrow + 8) * KST + ks * 8 + t];
            qa[ks][2] = Qs[qrow * KST + ks * 8 + t + 4];
            qa[ks][3] = Qs[(qrow + 8) * KST + ks * 8 + t + 4];
        }
    }
    __syncthreads();         // all done reading Q before V0 overwrites it

    issueV(0, 0); cp_commit();               // group: V0
    issueK(1, 1); issueV(1, 1); cp_commit(); // group: tile1

    float O[8][4];
    #pragma unroll
    for (int i = 0; i < 8; i++)
        #pragma unroll
        for (int j = 0; j < 4; j++) O[i][j] = 0.f;
    float m1 = -1e30f, m2 = -1e30f, l1 = 0.f, l2 = 0.f;

    uint32_t* const Ps = sm + PS_OFF + warp * (16 * PST);

    for (int kt = 0; kt < 32; kt++) {
        const int buf = kt & 1;
        if (kt < 31) cp_wait<1>(); else cp_wait<0>();
        __syncthreads();

        const uint32_t* Ks = sm + buf * (64 * KST);
        const uint32_t* Vs = sm + VS_OFF + buf * (64 * VST);

        // S = Q K^T  (16 x 64 per warp)
        float S[8][4];
        #pragma unroll
        for (int i = 0; i < 8; i++)
            #pragma unroll
            for (int j = 0; j < 4; j++) S[i][j] = 0.f;

        #pragma unroll
        for (int ks = 0; ks < 8; ks++) {
            #pragma unroll
            for (int nt = 0; nt < 8; nt++) {
                uint32_t bf[2];
                const int key = nt * 8 + g;
                bf[0] = Ks[key * KST + ks * 8 + t];
                bf[1] = Ks[key * KST + ks * 8 + t + 4];
                mma_tf32(S[nt], qa[ks], bf);
            }
        }

        // online softmax
        float rmax1 = -1e30f, rmax2 = -1e30f;
        #pragma unroll
        for (int nt = 0; nt < 8; nt++) {
            rmax1 = fmaxf(rmax1, fmaxf(S[nt][0], S[nt][1]));
            rmax2 = fmaxf(rmax2, fmaxf(S[nt][2], S[nt][3]));
        }
        rmax1 = fmaxf(rmax1, __shfl_xor_sync(0xffffffff, rmax1, 1));
        rmax1 = fmaxf(rmax1, __shfl_xor_sync(0xffffffff, rmax1, 2));
        rmax2 = fmaxf(rmax2, __shfl_xor_sync(0xffffffff, rmax2, 1));
        rmax2 = fmaxf(rmax2, __shfl_xor_sync(0xffffffff, rmax2, 2));

        const float mn1 = fmaxf(m1, rmax1);
        const float mn2 = fmaxf(m2, rmax2);
        const float cr1 = __expf(m1 - mn1);
        const float cr2 = __expf(m2 - mn2);

        float rs1 = 0.f, rs2 = 0.f;
        #pragma unroll
        for (int nt = 0; nt < 8; nt++) {
            S[nt][0] = __expf(S[nt][0] - mn1);
            S[nt][1] = __expf(S[nt][1] - mn1);
            S[nt][2] = __expf(S[nt][2] - mn2);
            S[nt][3] = __expf(S[nt][3] - mn2);
            rs1 += S[nt][0] + S[nt][1];
            rs2 += S[nt][2] + S[nt][3];
        }
        rs1 += __shfl_xor_sync(0xffffffff, rs1, 1);
        rs1 += __shfl_xor_sync(0xffffffff, rs1, 2);
        rs2 += __shfl_xor_sync(0xffffffff, rs2, 1);
        rs2 += __shfl_xor_sync(0xffffffff, rs2, 2);

        l1 = l1 * cr1 + rs1;
        l2 = l2 * cr2 + rs2;
        m1 = mn1; m2 = mn2;

        #pragma unroll
        for (int nt = 0; nt < 8; nt++) {
            O[nt][0] *= cr1; O[nt][1] *= cr1;
            O[nt][2] *= cr2; O[nt][3] *= cr2;
        }

        // re-fragment P via per-warp smem tile
        __syncwarp();
        #pragma unroll
        for (int nt = 0; nt < 8; nt++) {
            Ps[g * PST + nt * 8 + 2 * t]           = f2tf(S[nt][0]);
            Ps[g * PST + nt * 8 + 2 * t + 1]       = f2tf(S[nt][1]);
            Ps[(g + 8) * PST + nt * 8 + 2 * t]     = f2tf(S[nt][2]);
            Ps[(g + 8) * PST + nt * 8 + 2 * t + 1] = f2tf(S[nt][3]);
        }
        __syncwarp();

        // O += P V
        #pragma unroll
        for (int ks = 0; ks < 8; ks++) {
            uint32_t pa[4];
            pa[0] = Ps[g * PST + ks * 8 + t];
            pa[1] = Ps[(g + 8) * PST + ks * 8 + t];
            pa[2] = Ps[g * PST + ks * 8 + t + 4];
            pa[3] = Ps[(g + 8) * PST + ks * 8 + t + 4];
            #pragma unroll
            for (int nt = 0; nt < 8; nt++) {
                uint32_t bf[2];
                bf[0] = Vs[(ks * 8 + t) * VST + nt * 8 + g];
                bf[1] = Vs[(ks * 8 + t + 4) * VST + nt * 8 + g];
                mma_tf32(O[nt], pa, bf);
            }
        }
        __syncthreads();
        if (kt + 2 < 32) { issueK(buf, kt + 2); issueV(buf, kt + 2); cp_commit(); }
    }

    // epilogue: softmax norm + the reference's /sqrt(E)=32, write tf32
    const int b = bh / HH, h = bh % HH;
    const int q1 = q0 + warp * 16 + g;
    const int q2 = q1 + 8;
    const float i1 = 1.0f / (l1 * 32.0f);
    const float i2 = 1.0f / (l2 * 32.0f);
    uint32_t* d1 = g_AOt + ((size_t)(b * NN + q1)) * EE + h * DD;
    uint32_t* d2 = g_AOt + ((size_t)(b * NN + q2)) * EE + h * DD;
    #pragma unroll
    for (int nt = 0; nt < 8; nt++) {
        d1[nt * 8 + 2 * t]     = f2tf(O[nt][0] * i1);
        d1[nt * 8 + 2 * t + 1] = f2tf(O[nt][1] * i1);
        d2[nt * 8 + 2 * t]     = f2tf(O[nt][2] * i2);
        d2[nt * 8 + 2 * t + 1] = f2tf(O[nt][3] * i2);
    }
}

// ---------------------------------------------------------------------------
extern "C" void kernel_launch(void* const* d_in, const int* in_sizes, int n_in,
                              void* d_out, int out_size)
{
    const float* x  = (const float*)d_in[0];
    const float* Wq = (const float*)d_in[1];
    const float* bq = (const float*)d_in[2];
    const float* Wk = (const float*)d_in[3];
    const float* bk = (const float*)d_in[4];
    const float* Wv = (const float*)d_in[5];
    const float* bv = (const float*)d_in[6];
    const float* Wo = (const float*)d_in[7];
    const float* bo = (const float*)d_in[8];
    float* out = (float*)d_out;

    cudaFuncSetAttribute(gemm_tc, cudaFuncAttributeMaxDynamicSharedMemorySize, GEMM_SMEM);
    cudaFuncSetAttribute(attn_tc, cudaFuncAttributeMaxDynamicSharedMemorySize, ATTN_SMEM);

    conv_tf32<<<(MM*EE/4 + 255) / 256, 256>>>((const float4*)x, 0, MM*EE/4);
    conv_tf32<<<(EE*EE/4 + 255) / 256, 256>>>((const float4*)Wq, 1, EE*EE/4);
    conv_tf32<<<(EE*EE/4 + 255) / 256, 256>>>((const float4*)Wk, 2, EE*EE/4);
    conv_tf32<<<(EE*EE/4 + 255) / 256, 256>>>((const float4*)Wv, 3, EE*EE/4);
    conv_tf32<<<(EE*EE/4 + 255) / 256, 256>>>((const float4*)Wo, 4, EE*EE/4);

    gemm_tc<<<dim3(EE/128, MM/128, 3), 256, GEMM_SMEM>>>(bq, bk, bv, bo, nullptr, -1);
    attn_tc<<<dim3(BB*HH, NN/64), 128, ATTN_SMEM>>>();
    gemm_tc<<<dim3(EE/128, MM/128, 1), 256, GEMM_SMEM>>>(bq, bk, bv, bo, out, 3);
}

// round 7
// speedup vs baseline: 8.6030x; 2.0161x over previous
#include <cuda_runtime.h>
#include <cuda_fp16.h>
#include <cstdint>

#define BB 2
#define NN 2048
#define EE 1024
#define HH 16
#define DD 64
#define MM (BB*NN)

// Scratch: everything fp16 (same 10-bit mantissa as tf32 -> same accuracy).
__device__ __half g_Xh[MM*EE];          // x
__device__ __half g_Wh[4][EE*EE];       // Wq,Wk,Wv,Wo
__device__ __half g_Q[BB*HH*NN*DD];     // [b,h,n,d]
__device__ __half g_K[BB*HH*NN*DD];
__device__ __half g_V[BB*HH*NN*DD];
__device__ __half g_AOh[BB*NN*EE];      // attn out [b,n,e]

__device__ __forceinline__ void mma_f16(float* d, const uint32_t* a, const uint32_t* b) {
    asm volatile(
        "mma.sync.aligned.m16n8k16.row.col.f32.f16.f16.f32 "
        "{%0,%1,%2,%3}, {%4,%5,%6,%7}, {%8,%9}, {%0,%1,%2,%3};"
        : "+f"(d[0]), "+f"(d[1]), "+f"(d[2]), "+f"(d[3])
        : "r"(a[0]), "r"(a[1]), "r"(a[2]), "r"(a[3]), "r"(b[0]), "r"(b[1]));
}
__device__ __forceinline__ void ldsm4t(uint32_t& r0, uint32_t& r1, uint32_t& r2,
                                       uint32_t& r3, uint32_t a) {
    asm volatile("ldmatrix.sync.aligned.m8n8.x4.trans.shared.b16 {%0,%1,%2,%3}, [%4];"
        : "=r"(r0), "=r"(r1), "=r"(r2), "=r"(r3) : "r"(a));
}
__device__ __forceinline__ void cpa16(uint32_t s, const void* g) {
    asm volatile("cp.async.cg.shared.global [%0], [%1], 16;" :: "r"(s), "l"(g));
}
__device__ __forceinline__ void cp_commit() { asm volatile("cp.async.commit_group;"); }
template<int N> __device__ __forceinline__ void cp_wait() {
    asm volatile("cp.async.wait_group %0;" :: "n"(N));
}
__device__ __forceinline__ uint32_t pack_h2(float lo, float hi) {
    __half2 h = __floats2half2_rn(lo, hi);
    return *reinterpret_cast<uint32_t*>(&h);
}

// ---------------------------------------------------------------------------
// Fused fp32 -> fp16 convert: x (1M float4) + 4 W's (256K float4 each).
// ---------------------------------------------------------------------------
#define NX4 (MM*EE/4)       // 1048576
#define NW4 (EE*EE/4)       // 262144
__global__ __launch_bounds__(256)
void conv_h(const float4* __restrict__ x,  const float4* __restrict__ w0,
            const float4* __restrict__ w1, const float4* __restrict__ w2,
            const float4* __restrict__ w3)
{
    int i = blockIdx.x * 256 + threadIdx.x;
    const float4* src; __half* dst; int off;
    if (i < NX4) { src = x; dst = g_Xh; off = i; }
    else {
        int k = i - NX4;
        int j = k >> 18;            // NW4 = 2^18
        off = k & (NW4 - 1);
        src = (j == 0) ? w0 : (j == 1) ? w1 : (j == 2) ? w2 : w3;
        dst = g_Wh[j];
    }
    float4 v = src[off];
    __half2* d2 = (__half2*)(dst + (size_t)off * 4);
    d2[0] = __floats2half2_rn(v.x, v.y);
    d2[1] = __floats2half2_rn(v.z, v.w);
}

// ---------------------------------------------------------------------------
// fp16 GEMM: C[4096][1024] = X @ W^T + bias. 128x128 tiles, BK=32, 256 thr,
// 3-stage cp.async, m16n8k16. target=-1: QKV (tgt=blockIdx.z, fp16 split-head
// write); target=3: O-proj (X=g_AOh, fp32 write to outp).
// ---------------------------------------------------------------------------
#define GRS 40                    // smem row stride in halves (32 + 8 pad)
#define GSTH (128*GRS)            // 5120 halves per stage per matrix
#define GEMM_SMEM (6*GSTH*2)      // 61440 B

__global__ __launch_bounds__(256)
void gemm_h(const float* __restrict__ b0p, const float* __restrict__ b1p,
            const float* __restrict__ b2p, const float* __restrict__ b3p,
            float* __restrict__ outp, int target)
{
    const int tgt = (target < 0) ? (int)blockIdx.z : target;
    const __half* __restrict__ X = (tgt == 3) ? g_AOh : g_Xh;
    const __half* __restrict__ W = g_Wh[tgt];
    const float* __restrict__ bias = (tgt == 0) ? b0p : (tgt == 1) ? b1p : (tgt == 2) ? b2p : b3p;

    extern __shared__ __align__(16) __half smh[];
    const uint32_t* smw = (const uint32_t*)smh;         // word view
    const uint32_t sbA = (uint32_t)__cvta_generic_to_shared(smh);
    const uint32_t sbW = sbA + 3 * GSTH * 2;

    const int tid = threadIdx.x;
    const int warp = tid >> 5, lane = tid & 31;
    const int g = lane >> 2, t = lane & 3;
    const int m0 = blockIdx.y * 128, n0 = blockIdx.x * 128;
    const int wm = (warp >> 1) * 32, wn = (warp & 1) * 64;

    float acc[2][8][4];
    #pragma unroll
    for (int i = 0; i < 2; i++)
        #pragma unroll
        for (int j = 0; j < 8; j++)
            #pragma unroll
            for (int k = 0; k < 4; k++) acc[i][j][k] = 0.f;

    // per stage per matrix: 128 rows x 32 halves = 512 chunks of 16B; 2/thread
    auto issue = [&](int s, int kk) {
        #pragma unroll
        for (int i = 0; i < 2; i++) {
            const int idx = tid + i * 256;
            const int r = idx >> 2, c = (idx & 3) * 8;
            cpa16(sbA + (uint32_t)(s * GSTH + r * GRS + c) * 2,
                  X + (size_t)(m0 + r) * EE + kk * 32 + c);
            cpa16(sbW + (uint32_t)(s * GSTH + r * GRS + c) * 2,
                  W + (size_t)(n0 + r) * EE + kk * 32 + c);
        }
        cp_commit();
    };

    issue(0, 0);
    issue(1, 1);

    for (int kt = 0; kt < 32; kt++) {
        const int buf = kt % 3;
        if (kt < 31) cp_wait<1>(); else cp_wait<0>();
        __syncthreads();
        if (kt + 2 < 32) issue((kt + 2) % 3, kt + 2);

        const uint32_t* Ab = smw + buf * (GSTH / 2);
        const uint32_t* Wb = smw + 3 * (GSTH / 2) + buf * (GSTH / 2);
        #pragma unroll
        for (int ks = 0; ks < 2; ks++) {
            uint32_t af[2][4];
            #pragma unroll
            for (int mi = 0; mi < 2; mi++) {
                const int row = wm + mi * 16 + g;
                af[mi][0] = Ab[row * 20 + ks * 8 + t];
                af[mi][1] = Ab[(row + 8) * 20 + ks * 8 + t];
                af[mi][2] = Ab[row * 20 + ks * 8 + t + 4];
                af[mi][3] = Ab[(row + 8) * 20 + ks * 8 + t + 4];
            }
            #pragma unroll
            for (int nt = 0; nt < 8; nt++) {
                uint32_t bf[2];
                const int nr = wn + nt * 8 + g;
                bf[0] = Wb[nr * 20 + ks * 8 + t];
                bf[1] = Wb[nr * 20 + ks * 8 + t + 4];
                mma_f16(acc[0][nt], af[0], bf);
                mma_f16(acc[1][nt], af[1], bf);
            }
        }
        __syncthreads();
    }

    __half* dstQKV = (tgt == 0) ? g_Q : (tgt == 1) ? g_K : g_V;
    #pragma unroll
    for (int mi = 0; mi < 2; mi++) {
        #pragma unroll
        for (int nt = 0; nt < 8; nt++) {
            const int rbase = m0 + wm + mi * 16 + g;
            const int cbase = n0 + wn + nt * 8 + 2 * t;
            #pragma unroll
            for (int hh = 0; hh < 2; hh++) {
                const int m = rbase + hh * 8;
                const float v0 = acc[mi][nt][2 * hh + 0] + bias[cbase + 0];
                const float v1 = acc[mi][nt][2 * hh + 1] + bias[cbase + 1];
                if (tgt == 3) {
                    outp[m * EE + cbase + 0] = v0;
                    outp[m * EE + cbase + 1] = v1;
                } else {
                    const int b = m >> 11;
                    const int n = m & (NN - 1);
                    const int h = cbase >> 6;
                    const int d = cbase & (DD - 1);
                    *(__half2*)&dstQKV[((b * HH + h) * NN + n) * DD + d] =
                        __floats2half2_rn(v0, v1);
                }
            }
        }
    }
}

// ---------------------------------------------------------------------------
// Flash attention, fp16 m16n8k16, 64-key tiles, 2-stage cp.async.
// grid (B*H, N/64), block 128 (4 warps x 16 q-rows).
// smem (halves): K 2x4608 @0; V 2x4608 @9216 (Q staged in V stage 0);
// Ps 4x1152 @18432. Row stride 72 halves -> bank(word) = 4g+t, conflict-free.
// ---------------------------------------------------------------------------
#define KSTAGE_H 4608                      // 64*72 halves
#define ATTN_SMEM ((18432 + 4*1152) * 2)   // 46080 B

__global__ __launch_bounds__(128)
void attn_h()
{
    extern __shared__ __align__(16) __half smh[];
    const uint32_t* smw = (const uint32_t*)smh;
    uint32_t* smw_mut = (uint32_t*)smh;
    const uint32_t sb = (uint32_t)__cvta_generic_to_shared(smh);

    const int bh = blockIdx.x;
    const int q0 = blockIdx.y * 64;
    const int tid = threadIdx.x, warp = tid >> 5, lane = tid & 31;
    const int g = lane >> 2, t = lane & 3;

    const __half* __restrict__ Qp = g_Q + (size_t)bh * NN * DD;
    const __half* __restrict__ Kp = g_K + (size_t)bh * NN * DD;
    const __half* __restrict__ Vp = g_V + (size_t)bh * NN * DD;

    // tile = 64 rows x 64 halves = 512 x 16B chunks; 4 per thread
    auto issueK = [&](int s, int kk) {
        const uint32_t off = sb + (uint32_t)(s * KSTAGE_H) * 2;
        #pragma unroll
        for (int i = 0; i < 4; i++) {
            const int idx = tid + i * 128;
            const int r = idx >> 3, c = (idx & 7) * 8;
            cpa16(off + (uint32_t)(r * 72 + c) * 2, Kp + (size_t)(kk * 64 + r) * DD + c);
        }
    };
    auto issueV = [&](int s, int kk) {
        const uint32_t off = sb + (uint32_t)(9216 + s * KSTAGE_H) * 2;
        #pragma unroll
        for (int i = 0; i < 4; i++) {
            const int idx = tid + i * 128;
            const int r = idx >> 3, c = (idx & 7) * 8;
            cpa16(off + (uint32_t)(r * 72 + c) * 2, Vp + (size_t)(kk * 64 + r) * DD + c);
        }
    };

    // Q -> V stage-0 region; K tile0 -> K stage 0
    {
        const uint32_t qoff = sb + (uint32_t)9216 * 2;
        #pragma unroll
        for (int i = 0; i < 4; i++) {
            const int idx = tid + i * 128;
            const int r = idx >> 3, c = (idx & 7) * 8;
            cpa16(qoff + (uint32_t)(r * 72 + c) * 2, Qp + (size_t)(q0 + r) * DD + c);
        }
        cp_commit();
        issueK(0, 0);
        cp_commit();
    }
    cp_wait<1>();
    __syncthreads();

    // hoist Q a-fragments (4 k-steps of 16)
    uint32_t qa[4][4];
    {
        const uint32_t* Qw = smw + 4608;       // 9216 halves / 2
        const int qrow = warp * 16 + g;
        #pragma unroll
        for (int ks = 0; ks < 4; ks++) {
            qa[ks][0] = Qw[qrow * 36 + ks * 8 + t];
            qa[ks][1] = Qw[(qrow + 8) * 36 + ks * 8 + t];
            qa[ks][2] = Qw[qrow * 36 + ks * 8 + t + 4];
            qa[ks][3] = Qw[(qrow + 8) * 36 + ks * 8 + t + 4];
        }
    }
    __syncthreads();

    issueV(0, 0); cp_commit();
    issueK(1, 1); issueV(1, 1); cp_commit();

    float O[8][4];
    #pragma unroll
    for (int i = 0; i < 8; i++)
        #pragma unroll
        for (int j = 0; j < 4; j++) O[i][j] = 0.f;
    float m1 = -1e30f, m2 = -1e30f, l1 = 0.f, l2 = 0.f;

    uint32_t* const Pw = smw_mut + 9216 + warp * 576;   // per-warp P tile (16x72 halves)
    // per-lane ldmatrix.trans address component for V
    const int llo = lane & 7, sel = lane >> 3;
    const uint32_t vlane = (uint32_t)(((sel & 1) * 8 + llo) * 72 + (sel >> 1) * 8) * 2;

    for (int kt = 0; kt < 32; kt++) {
        const int buf = kt & 1;
        if (kt < 31) cp_wait<1>(); else cp_wait<0>();
        __syncthreads();

        const uint32_t* Kw = smw + buf * (KSTAGE_H / 2);
        const uint32_t vstage = sb + (uint32_t)(9216 + buf * KSTAGE_H) * 2;

        // S = Q K^T  (16 x 64 per warp), k-steps of 16
        float S[8][4];
        #pragma unroll
        for (int i = 0; i < 8; i++)
            #pragma unroll
            for (int j = 0; j < 4; j++) S[i][j] = 0.f;

        #pragma unroll
        for (int ks = 0; ks < 4; ks++) {
            #pragma unroll
            for (int nt = 0; nt < 8; nt++) {
                uint32_t bf[2];
                const int key = nt * 8 + g;
                bf[0] = Kw[key * 36 + ks * 8 + t];
                bf[1] = Kw[key * 36 + ks * 8 + t + 4];
                mma_f16(S[nt], qa[ks], bf);
            }
        }

        // online softmax
        float rmax1 = -1e30f, rmax2 = -1e30f;
        #pragma unroll
        for (int nt = 0; nt < 8; nt++) {
            rmax1 = fmaxf(rmax1, fmaxf(S[nt][0], S[nt][1]));
            rmax2 = fmaxf(rmax2, fmaxf(S[nt][2], S[nt][3]));
        }
        rmax1 = fmaxf(rmax1, __shfl_xor_sync(0xffffffff, rmax1, 1));
        rmax1 = fmaxf(rmax1, __shfl_xor_sync(0xffffffff, rmax1, 2));
        rmax2 = fmaxf(rmax2, __shfl_xor_sync(0xffffffff, rmax2, 1));
        rmax2 = fmaxf(rmax2, __shfl_xor_sync(0xffffffff, rmax2, 2));

        const float mn1 = fmaxf(m1, rmax1);
        const float mn2 = fmaxf(m2, rmax2);
        const float cr1 = __expf(m1 - mn1);
        const float cr2 = __expf(m2 - mn2);

        float rs1 = 0.f, rs2 = 0.f;
        #pragma unroll
        for (int nt = 0; nt < 8; nt++) {
            S[nt][0] = __expf(S[nt][0] - mn1);
            S[nt][1] = __expf(S[nt][1] - mn1);
            S[nt][2] = __expf(S[nt][2] - mn2);
            S[nt][3] = __expf(S[nt][3] - mn2);
            rs1 += S[nt][0] + S[nt][1];
            rs2 += S[nt][2] + S[nt][3];
        }
        rs1 += __shfl_xor_sync(0xffffffff, rs1, 1);
        rs1 += __shfl_xor_sync(0xffffffff, rs1, 2);
        rs2 += __shfl_xor_sync(0xffffffff, rs2, 1);
        rs2 += __shfl_xor_sync(0xffffffff, rs2, 2);

        l1 = l1 * cr1 + rs1;
        l2 = l2 * cr2 + rs2;
        m1 = mn1; m2 = mn2;

        #pragma unroll
        for (int nt = 0; nt < 8; nt++) {
            O[nt][0] *= cr1; O[nt][1] *= cr1;
            O[nt][2] *= cr2; O[nt][3] *= cr2;
        }

        // P -> fp16 per-warp smem tile (half2 stores)
        __syncwarp();
        #pragma unroll
        for (int nt = 0; nt < 8; nt++) {
            Pw[g * 36 + nt * 4 + t]       = pack_h2(S[nt][0], S[nt][1]);
            Pw[(g + 8) * 36 + nt * 4 + t] = pack_h2(S[nt][2], S[nt][3]);
        }
        __syncwarp();

        // O += P V  (V b-frags via ldmatrix.x4.trans)
        #pragma unroll
        for (int ks = 0; ks < 4; ks++) {
            uint32_t pa[4];
            pa[0] = Pw[g * 36 + ks * 8 + t];
            pa[1] = Pw[(g + 8) * 36 + ks * 8 + t];
            pa[2] = Pw[g * 36 + ks * 8 + t + 4];
            pa[3] = Pw[(g + 8) * 36 + ks * 8 + t + 4];
            #pragma unroll
            for (int p = 0; p < 4; p++) {
                uint32_t b0, b1, b2, b3;
                ldsm4t(b0, b1, b2, b3, vstage + vlane + ks * 2304 + p * 32);
                uint32_t bA[2] = {b0, b1}, bB[2] = {b2, b3};
                mma_f16(O[2 * p],     pa, bA);
                mma_f16(O[2 * p + 1], pa, bB);
            }
        }
        __syncthreads();
        if (kt + 2 < 32) { issueK(buf, kt + 2); issueV(buf, kt + 2); cp_commit(); }
    }

    // epilogue: softmax norm + reference's /sqrt(E)=32; write fp16
    const int b = bh / HH, h = bh % HH;
    const int q1 = q0 + warp * 16 + g;
    const int q2 = q1 + 8;
    const float i1 = 1.0f / (l1 * 32.0f);
    const float i2 = 1.0f / (l2 * 32.0f);
    __half2* d1 = (__half2*)(g_AOh + ((size_t)(b * NN + q1)) * EE + h * DD);
    __half2* d2 = (__half2*)(g_AOh + ((size_t)(b * NN + q2)) * EE + h * DD);
    #pragma unroll
    for (int nt = 0; nt < 8; nt++) {
        d1[nt * 4 + t] = __floats2half2_rn(O[nt][0] * i1, O[nt][1] * i1);
        d2[nt * 4 + t] = __floats2half2_rn(O[nt][2] * i2, O[nt][3] * i2);
    }
}

// ---------------------------------------------------------------------------
extern "C" void kernel_launch(void* const* d_in, const int* in_sizes, int n_in,
                              void* d_out, int out_size)
{
    const float* x  = (const float*)d_in[0];
    const float* Wq = (const float*)d_in[1];
    const float* bq = (const float*)d_in[2];
    const float* Wk = (const float*)d_in[3];
    const float* bk = (const float*)d_in[4];
    const float* Wv = (const float*)d_in[5];
    const float* bv = (const float*)d_in[6];
    const float* Wo = (const float*)d_in[7];
    const float* bo = (const float*)d_in[8];
    float* out = (float*)d_out;

    cudaFuncSetAttribute(gemm_h, cudaFuncAttributeMaxDynamicSharedMemorySize, GEMM_SMEM);
    cudaFuncSetAttribute(attn_h, cudaFuncAttributeMaxDynamicSharedMemorySize, ATTN_SMEM);

    const int total4 = NX4 + 4 * NW4;     // 2097152
    conv_h<<<total4 / 256, 256>>>((const float4*)x, (const float4*)Wq,
                                  (const float4*)Wk, (const float4*)Wv,
                                  (const float4*)Wo);

    gemm_h<<<dim3(EE/128, MM/128, 3), 256, GEMM_SMEM>>>(bq, bk, bv, bo, nullptr, -1);
    attn_h<<<dim3(BB*HH, NN/64), 128, ATTN_SMEM>>>();
    gemm_h<<<dim3(EE/128, MM/128, 1), 256, GEMM_SMEM>>>(bq, bk, bv, bo, out, 3);
}